// round 2
// baseline (speedup 1.0000x reference)
#include <cuda_runtime.h>

#define BS    512
#define NN    256
#define MAXIT 200
#define OMEGA 1.5f

// 128 MB scratch: g_AT[b][j][i] = OMEGA * A[b][i][j]  (columns contiguous)
__device__ float g_AT[(size_t)BS * NN * NN];
__device__ float g_X[BS * NN];   // saved iterate after phase 0
__device__ int   g_tc[BS];       // per-batch sweeps completed in phase 0
__device__ int   g_T;            // global sweep count = max_b g_tc[b]

__device__ __forceinline__ float warp_sum(float v) {
#pragma unroll
    for (int o = 16; o > 0; o >>= 1) v += __shfl_xor_sync(0xffffffffu, v, o);
    return v;
}

// ---------------------------------------------------------------------------
// Transpose + pre-scale by omega; also resets g_T each replay.
// ---------------------------------------------------------------------------
__global__ void k_transpose(const float* __restrict__ A) {
    __shared__ float tile[32][33];
    int b = blockIdx.z, i0 = blockIdx.x * 32, j0 = blockIdx.y * 32;
    const float* Ab  = A    + (size_t)b * NN * NN;
    float*       ATb = g_AT + (size_t)b * NN * NN;
#pragma unroll
    for (int r = threadIdx.y; r < 32; r += 8)
        tile[r][threadIdx.x] = Ab[(size_t)(i0 + r) * NN + j0 + threadIdx.x];
    __syncthreads();
#pragma unroll
    for (int r = threadIdx.y; r < 32; r += 8)
        ATb[(size_t)(j0 + r) * NN + i0 + threadIdx.x] = OMEGA * tile[threadIdx.x][r];
    if (blockIdx.x == 0 && blockIdx.y == 0 && blockIdx.z == 0 &&
        threadIdx.x == 0 && threadIdx.y == 0)
        g_T = 0;
}

// ---------------------------------------------------------------------------
// One SOR sweep: solve (D+wL)x_new = (1-w)D x + w b - wU x. Returns ||xs-x_new||.
// One warp per batch; lane owns rows [8*lane, 8*lane+8).
// ---------------------------------------------------------------------------
__device__ float sor_sweep(const float* __restrict__ ATb, float* x_sm,
                           const float* dcoef, const float* invd,
                           const float* wb, const float* xs, int lane) {
    int rb = lane * 8;
    float acc[8];
#pragma unroll
    for (int s = 0; s < 8; s++) acc[s] = fmaf(dcoef[s], x_sm[rb + s], wb[s]);

    // Upper sweep: acc_i -= wA[i][j] * x_old[j] for j > i. Chain-free.
#pragma unroll 4
    for (int j = 1; j < NN; j++) {
        if (j > rb) {
            const float4* cp = reinterpret_cast<const float4*>(ATb + (size_t)j * NN + rb);
            float4 a0 = cp[0], a1 = cp[1];
            float  xj = x_sm[j];
            float a[8] = {a0.x, a0.y, a0.z, a0.w, a1.x, a1.y, a1.z, a1.w};
#pragma unroll
            for (int s = 0; s < 8; s++)
                if (rb + s < j) acc[s] = fmaf(-a[s], xj, acc[s]);
        }
    }
    __syncwarp();

    // Lower sweep: 8x8-blocked forward substitution.
    float xnew[8];
#pragma unroll 1
    for (int jb = 0; jb < 32; jb++) {
        float4 cur[16];                       // 8 cols x 8 rows of this lane
        if (lane >= jb) {
            const float4* bp = reinterpret_cast<const float4*>(ATb + (size_t)jb * 8 * NN + rb);
#pragma unroll
            for (int c = 0; c < 8; c++) {
                cur[2 * c]     = bp[c * (NN / 4)];
                cur[2 * c + 1] = bp[c * (NN / 4) + 1];
            }
        }
        float xv[8];
#pragma unroll
        for (int u = 0; u < 8; u++) xv[u] = 0.0f;
        if (lane == jb) {                     // serial 8x8 diagonal solve
#pragma unroll
            for (int u = 0; u < 8; u++) {
                float x = acc[u] * invd[u];
                xv[u] = x;
                float a[8] = {cur[2*u].x, cur[2*u].y, cur[2*u].z, cur[2*u].w,
                              cur[2*u+1].x, cur[2*u+1].y, cur[2*u+1].z, cur[2*u+1].w};
#pragma unroll
                for (int s = 0; s < 8; s++)
                    if (s > u) acc[s] = fmaf(-a[s], x, acc[s]);
            }
#pragma unroll
            for (int u = 0; u < 8; u++) { xnew[u] = xv[u]; x_sm[rb + u] = xv[u]; }
        }
        float xjv[8];
#pragma unroll
        for (int u = 0; u < 8; u++) xjv[u] = __shfl_sync(0xffffffffu, xv[u], jb);
        if (lane > jb) {                      // rank-8 update
#pragma unroll
            for (int c = 0; c < 8; c++) {
                float a[8] = {cur[2*c].x, cur[2*c].y, cur[2*c].z, cur[2*c].w,
                              cur[2*c+1].x, cur[2*c+1].y, cur[2*c+1].z, cur[2*c+1].w};
#pragma unroll
                for (int s = 0; s < 8; s++) acc[s] = fmaf(-a[s], xjv[c], acc[s]);
            }
        }
    }
    __syncwarp();                             // order x_sm writes for next sweep
    float e2 = 0.0f;
#pragma unroll
    for (int s = 0; s < 8; s++) { float d = xs[s] - xnew[s]; e2 += d * d; }
    return sqrtf(warp_sum(e2));
}

// ---------------------------------------------------------------------------
// phase 0: iterate each batch to its own convergence; record t_b, atomicMax T.
// phase 1: resume each batch from saved state up to global T; zero the tail.
// ---------------------------------------------------------------------------
__global__ void __launch_bounds__(32) k_sor(const float* __restrict__ A,
                                            const float* __restrict__ bv,
                                            const float* __restrict__ xsol,
                                            const float* __restrict__ theta,
                                            const float* __restrict__ rtol,
                                            float* __restrict__ out, int phase) {
    __shared__ float x_sm[NN];
    int b = blockIdx.x, lane = threadIdx.x, rb = lane * 8;
    const float* Ab  = A    + (size_t)b * NN * NN;
    const float* ATb = g_AT + (size_t)b * NN * NN;

    float invd[8], dcoef[8], wb[8], xs[8];
#pragma unroll
    for (int s = 0; s < 8; s++) {
        int r = rb + s;
        float d  = Ab[(size_t)r * NN + r];
        invd[s]  = 1.0f / d;
        dcoef[s] = (1.0f - OMEGA) * d;
        wb[s]    = OMEGA * bv[b * NN + r];
        xs[s]    = xsol[b * NN + r];
    }
    float nx2 = 0.0f;
#pragma unroll
    for (int s = 0; s < 8; s++) nx2 += xs[s] * xs[s];
    float  xtol = rtol[b] * sqrtf(warp_sum(nx2));
    float* outb = out + (size_t)b * (MAXIT + 1);

    if (phase == 0) {
        float e2 = 0.0f;
#pragma unroll
        for (int s = 0; s < 8; s++) {
            float xv = theta[b * NN + rb + s];
            x_sm[rb + s] = xv;
            float dd = xs[s] - xv;
            e2 += dd * dd;
        }
        float err = sqrtf(warp_sum(e2));
        if (lane == 0) outb[0] = err;
        __syncwarp();
        int t = 0;
        while (err > xtol && t < MAXIT) {     // err is warp-uniform
            t++;
            err = sor_sweep(ATb, x_sm, dcoef, invd, wb, xs, lane);
            if (lane == 0) outb[t] = err;
        }
#pragma unroll
        for (int s = 0; s < 8; s++) g_X[b * NN + rb + s] = x_sm[rb + s];
        if (lane == 0) { g_tc[b] = t; atomicMax(&g_T, t); }
    } else {
        int T = g_T, t = g_tc[b];
#pragma unroll
        for (int s = 0; s < 8; s++) x_sm[rb + s] = g_X[b * NN + rb + s];
        __syncwarp();
        while (t < T) {
            t++;
            float err = sor_sweep(ATb, x_sm, dcoef, invd, wb, xs, lane);
            if (lane == 0) outb[t] = err;
        }
        for (int t2 = T + 1 + lane; t2 <= MAXIT; t2 += 32) outb[t2] = 0.0f;
    }
}

extern "C" void kernel_launch(void* const* d_in, const int* in_sizes, int n_in,
                              void* d_out, int out_size) {
    const float* A     = (const float*)d_in[0];
    const float* bv    = (const float*)d_in[1];
    const float* xsol  = (const float*)d_in[2];
    const float* theta = (const float*)d_in[3];
    const float* rtol  = (const float*)d_in[4];
    float*       out   = (float*)d_out;

    k_transpose<<<dim3(NN / 32, NN / 32, BS), dim3(32, 8)>>>(A);
    k_sor<<<BS, 32>>>(A, bv, xsol, theta, rtol, out, 0);
    k_sor<<<BS, 32>>>(A, bv, xsol, theta, rtol, out, 1);
}

// round 4
// speedup vs baseline: 4.6226x; 4.6226x over previous
#include <cuda_runtime.h>

#define BS    512
#define NN    256
#define MAXIT 200
#define OMEGA 1.5f

// 128 MB scratch: G row-major per batch. e-iteration state, stop bookkeeping.
__device__ float g_G[(size_t)BS * NN * NN];
__device__ float g_E[BS * NN];
__device__ int   g_tc[BS];
__device__ int   g_T;

__device__ __forceinline__ float warp_sum(float v) {
#pragma unroll
    for (int o = 16; o > 0; o >>= 1) v += __shfl_xor_sync(0xffffffffu, v, o);
    return v;
}

// ---------------------------------------------------------------------------
// k_pre: per batch, solve (D + wL) G = -(wU + (w-1)D), 256 RHS columns.
// Thread = column c. Blocked (8 blocks of 32 rows) forward substitution:
// per block, acc[32] registers hold this column's partial rows; left-looking
// updates read previously written G rows (thread reads ONLY its own column ->
// no cross-thread global visibility needed beyond __syncthreads).
// ---------------------------------------------------------------------------
__global__ void __launch_bounds__(256) k_pre(const float* __restrict__ A) {
    __shared__ float shL[32][33];
    __shared__ float sh_invd[NN];
    int b = blockIdx.x;
    int c = threadIdx.x;
    const float* Ab = A   + (size_t)b * NN * NN;
    float*       Gb = g_G + (size_t)b * NN * NN;

    sh_invd[c] = 1.0f / Ab[(size_t)c * NN + c];
    if (b == 0 && c == 0) g_T = 0;          // reset before phase-0 atomicMax
    __syncthreads();

#pragma unroll 1
    for (int blk = 0; blk < 8; blk++) {
        int r0 = blk * 32;
        float acc[32];
        // RHS init: -(wU + (w-1)D) entries for rows r0..r0+31, column c.
#pragma unroll
        for (int k = 0; k < 32; k++) {
            int r = r0 + k;
            float a = Ab[(size_t)r * NN + c];          // coalesced
            acc[k] = (c > r) ? -OMEGA * a : ((c == r) ? -(OMEGA - 1.0f) * a : 0.0f);
        }
        // Left-looking update with already-solved rows (32-wide j tiles).
#pragma unroll 1
        for (int j0 = 0; j0 < r0; j0 += 32) {
            __syncthreads();
            for (int t = threadIdx.x; t < 32 * 32; t += 256) {
                int k = t >> 5, jj = t & 31;
                shL[k][jj] = OMEGA * Ab[(size_t)(r0 + k) * NN + j0 + jj];
            }
            __syncthreads();
#pragma unroll 4
            for (int jj = 0; jj < 32; jj++) {
                float yv = Gb[(size_t)(j0 + jj) * NN + c];   // own column, coalesced
#pragma unroll
                for (int k = 0; k < 32; k++)
                    acc[k] = fmaf(-shL[k][jj], yv, acc[k]);
            }
        }
        // Diagonal 32x32 block: serial-in-thread triangular solve.
        __syncthreads();
        for (int t = threadIdx.x; t < 32 * 32; t += 256) {
            int k = t >> 5, jj = t & 31;
            shL[k][jj] = OMEGA * Ab[(size_t)(r0 + k) * NN + r0 + jj];
        }
        __syncthreads();
#pragma unroll
        for (int k = 0; k < 32; k++) {
            float y = acc[k] * sh_invd[r0 + k];
            Gb[(size_t)(r0 + k) * NN + c] = y;         // coalesced row write
#pragma unroll
            for (int m = k + 1; m < 32; m++)
                acc[m] = fmaf(-shL[m][k], y, acc[m]);
        }
    }
}

// ---------------------------------------------------------------------------
// One e <- G e step. CTA = 256 thr, 8 warps; warp w owns rows [32w, 32w+32).
// Coalesced 1KB row reads, warp-shuffle dot reduce. Returns ||e_new|| (uniform).
// ---------------------------------------------------------------------------
__device__ float iter_step(const float* __restrict__ Gb, float* e_sm, float* red,
                           int wid, int lane) {
    float4 ev0 = *reinterpret_cast<const float4*>(&e_sm[lane * 8]);
    float4 ev1 = *reinterpret_cast<const float4*>(&e_sm[lane * 8 + 4]);
    float myval = 0.0f;
#pragma unroll 4
    for (int rr = 0; rr < 32; rr++) {
        int row = (wid << 5) + rr;
        const float4* gp = reinterpret_cast<const float4*>(Gb + (size_t)row * NN + lane * 8);
        float4 a0 = gp[0], a1 = gp[1];
        float s = a0.x * ev0.x + a0.y * ev0.y + a0.z * ev0.z + a0.w * ev0.w
                + a1.x * ev1.x + a1.y * ev1.y + a1.z * ev1.z + a1.w * ev1.w;
        s = warp_sum(s);
        if (lane == rr) myval = s;
    }
    __syncthreads();                                  // all e_sm reads done
    e_sm[(wid << 5) + lane] = myval;                  // == e_sm[tid]
    float p = warp_sum(myval * myval);
    if (lane == 0) red[wid] = p;
    __syncthreads();                                  // e_sm + red published
    float tot = red[0] + red[1] + red[2] + red[3] + red[4] + red[5] + red[6] + red[7];
    return sqrtf(tot);
}

// ---------------------------------------------------------------------------
// phase 0: per batch iterate until own err <= xtol; record t_b, atomicMax T.
// phase 1: resume from saved state to global T; zero tail columns.
// ---------------------------------------------------------------------------
__global__ void __launch_bounds__(256) k_iter(const float* __restrict__ xsol,
                                              const float* __restrict__ theta,
                                              const float* __restrict__ rtol,
                                              float* __restrict__ out, int phase) {
    __shared__ float e_sm[NN];
    __shared__ float red[8];
    int b = blockIdx.x;
    int tid = threadIdx.x, wid = tid >> 5, lane = tid & 31;
    const float* Gb   = g_G + (size_t)b * NN * NN;
    float*       outb = out + (size_t)b * (MAXIT + 1);

    // xtol = rtol * ||x_sol||
    float xv = xsol[b * NN + tid];
    float p = warp_sum(xv * xv);
    if (lane == 0) red[wid] = p;
    __syncthreads();
    float xtol = rtol[b] * sqrtf(red[0] + red[1] + red[2] + red[3] +
                                 red[4] + red[5] + red[6] + red[7]);
    __syncthreads();                                  // red reuse guard

    if (phase == 0) {
        float e0 = theta[b * NN + tid] - xv;
        e_sm[tid] = e0;
        float q = warp_sum(e0 * e0);
        if (lane == 0) red[wid] = q;
        __syncthreads();
        float err = sqrtf(red[0] + red[1] + red[2] + red[3] +
                          red[4] + red[5] + red[6] + red[7]);
        if (tid == 0) outb[0] = err;
        __syncthreads();
        int t = 0;
        while (err > xtol && t < MAXIT) {             // err uniform across CTA
            t++;
            err = iter_step(Gb, e_sm, red, wid, lane);
            if (tid == 0) outb[t] = err;
        }
        g_E[b * NN + tid] = e_sm[tid];
        if (tid == 0) { g_tc[b] = t; atomicMax(&g_T, t); }
    } else {
        int T = g_T, t = g_tc[b];
        e_sm[tid] = g_E[b * NN + tid];
        __syncthreads();
        while (t < T) {
            t++;
            float err = iter_step(Gb, e_sm, red, wid, lane);
            if (tid == 0) outb[t] = err;
        }
        for (int t2 = T + 1 + tid; t2 <= MAXIT; t2 += 256) outb[t2] = 0.0f;
    }
}

extern "C" void kernel_launch(void* const* d_in, const int* in_sizes, int n_in,
                              void* d_out, int out_size) {
    const float* A     = (const float*)d_in[0];
    const float* xsol  = (const float*)d_in[2];
    const float* theta = (const float*)d_in[3];
    const float* rtol  = (const float*)d_in[4];
    float*       out   = (float*)d_out;

    k_pre <<<BS, 256>>>(A);
    k_iter<<<BS, 256>>>(xsol, theta, rtol, out, 0);
    k_iter<<<BS, 256>>>(xsol, theta, rtol, out, 1);
}

// round 5
// speedup vs baseline: 8.3242x; 1.8008x over previous
#include <cuda_runtime.h>
#include <cuda_fp16.h>

#define BS    512
#define NN    256
#define MAXIT 200
#define OMEGA 1.5f

// fp32 G (solve-accurate, read by left-looking updates), fp16 copy for iteration.
__device__ float  g_G [(size_t)BS * NN * NN];   // 128 MB
__device__ __half g_Gh[(size_t)BS * NN * NN];   // 64 MB (L2-resident)
__device__ float  g_E[BS * NN];
__device__ int    g_tc[BS];
__device__ int    g_T;

__device__ __forceinline__ float warp_sum(float v) {
#pragma unroll
    for (int o = 16; o > 0; o >>= 1) v += __shfl_xor_sync(0xffffffffu, v, o);
    return v;
}

// ---------------------------------------------------------------------------
// k_pre: solve (D + wL) G = -(wU + (w-1)D), 256 RHS columns per batch.
// 128 threads; thread t owns columns 2t, 2t+1 -> each shL element feeds 2 FMAs.
// Writes fp32 G (for the solve's own left-looking reads) and fp16 G (for iter).
// ---------------------------------------------------------------------------
__global__ void __launch_bounds__(128) k_pre(const float* __restrict__ A) {
    __shared__ float shL[32][33];
    __shared__ float sh_invd[NN];
    int b = blockIdx.x, t = threadIdx.x;
    int c0 = 2 * t;
    const float* Ab = A    + (size_t)b * NN * NN;
    float*       Gb = g_G  + (size_t)b * NN * NN;
    __half*      Gh = g_Gh + (size_t)b * NN * NN;

    for (int i = t; i < NN; i += 128)
        sh_invd[i] = 1.0f / Ab[(size_t)i * NN + i];
    if (b == 0 && t == 0) g_T = 0;           // reset before phase-0 atomicMax
    __syncthreads();

#pragma unroll 1
    for (int blk = 0; blk < 8; blk++) {
        int r0 = blk * 32;
        float acc0[32], acc1[32];
        // RHS init: -(wU + (w-1)D) rows r0..r0+31, columns c0, c0+1.
#pragma unroll
        for (int k = 0; k < 32; k++) {
            int r = r0 + k;
            float2 a = *reinterpret_cast<const float2*>(Ab + (size_t)r * NN + c0);
            acc0[k] = (c0     > r) ? -OMEGA * a.x : ((c0     == r) ? -(OMEGA - 1.f) * a.x : 0.f);
            acc1[k] = (c0 + 1 > r) ? -OMEGA * a.y : ((c0 + 1 == r) ? -(OMEGA - 1.f) * a.y : 0.f);
        }
        // Left-looking update with already-solved rows (32-wide j tiles).
#pragma unroll 1
        for (int j0 = 0; j0 < r0; j0 += 32) {
            __syncthreads();
            for (int e = t; e < 32 * 32; e += 128) {
                int k = e >> 5, jj = e & 31;
                shL[k][jj] = OMEGA * Ab[(size_t)(r0 + k) * NN + j0 + jj];
            }
            __syncthreads();
#pragma unroll 4
            for (int jj = 0; jj < 32; jj++) {
                float2 yv = *reinterpret_cast<const float2*>(Gb + (size_t)(j0 + jj) * NN + c0);
#pragma unroll
                for (int k = 0; k < 32; k++) {
                    float l = shL[k][jj];
                    acc0[k] = fmaf(-l, yv.x, acc0[k]);
                    acc1[k] = fmaf(-l, yv.y, acc1[k]);
                }
            }
        }
        // Diagonal 32x32 block: serial-in-thread triangular solve.
        __syncthreads();
        for (int e = t; e < 32 * 32; e += 128) {
            int k = e >> 5, jj = e & 31;
            shL[k][jj] = OMEGA * Ab[(size_t)(r0 + k) * NN + r0 + jj];
        }
        __syncthreads();
#pragma unroll
        for (int k = 0; k < 32; k++) {
            float inv = sh_invd[r0 + k];
            float y0 = acc0[k] * inv;
            float y1 = acc1[k] * inv;
            *reinterpret_cast<float2*>(Gb + (size_t)(r0 + k) * NN + c0) = make_float2(y0, y1);
            *reinterpret_cast<__half2*>(Gh + (size_t)(r0 + k) * NN + c0) = __floats2half2_rn(y0, y1);
#pragma unroll
            for (int m = k + 1; m < 32; m++) {
                float l = shL[m][k];
                acc0[m] = fmaf(-l, y0, acc0[m]);
                acc1[m] = fmaf(-l, y1, acc1[m]);
            }
        }
    }
}

// ---------------------------------------------------------------------------
// One e <- G e step on fp16 G, fp32 accumulation. CTA = 8 warps; warp w owns
// rows [32w, 32w+32); lane reads 8 cols (16B). Returns ||e_new|| (CTA-uniform).
// ---------------------------------------------------------------------------
__device__ float iter_step(const __half* __restrict__ Gh, float* e_sm, float* red,
                           int wid, int lane) {
    float4 ev0 = *reinterpret_cast<const float4*>(&e_sm[lane * 8]);
    float4 ev1 = *reinterpret_cast<const float4*>(&e_sm[lane * 8 + 4]);
    float myval = 0.0f;
#pragma unroll 4
    for (int rr = 0; rr < 32; rr++) {
        int row = (wid << 5) + rr;
        uint4 raw = *reinterpret_cast<const uint4*>(Gh + (size_t)row * NN + lane * 8);
        float2 f0 = __half22float2(*reinterpret_cast<__half2*>(&raw.x));
        float2 f1 = __half22float2(*reinterpret_cast<__half2*>(&raw.y));
        float2 f2 = __half22float2(*reinterpret_cast<__half2*>(&raw.z));
        float2 f3 = __half22float2(*reinterpret_cast<__half2*>(&raw.w));
        float s = f0.x * ev0.x + f0.y * ev0.y + f1.x * ev0.z + f1.y * ev0.w
                + f2.x * ev1.x + f2.y * ev1.y + f3.x * ev1.z + f3.y * ev1.w;
        s = warp_sum(s);
        if (lane == rr) myval = s;
    }
    __syncthreads();                              // all e_sm reads done
    e_sm[(wid << 5) + lane] = myval;
    float p = warp_sum(myval * myval);
    if (lane == 0) red[wid] = p;
    __syncthreads();
    float tot = red[0] + red[1] + red[2] + red[3] + red[4] + red[5] + red[6] + red[7];
    return sqrtf(tot);
}

// ---------------------------------------------------------------------------
// phase 0: per batch iterate until own err <= xtol; record t_b, atomicMax T.
// phase 1: resume from saved state to global T; zero tail columns.
// ---------------------------------------------------------------------------
__global__ void __launch_bounds__(256) k_iter(const float* __restrict__ xsol,
                                              const float* __restrict__ theta,
                                              const float* __restrict__ rtol,
                                              float* __restrict__ out, int phase) {
    __shared__ float e_sm[NN];
    __shared__ float red[8];
    int b = blockIdx.x;
    int tid = threadIdx.x, wid = tid >> 5, lane = tid & 31;
    const __half* Gh   = g_Gh + (size_t)b * NN * NN;
    float*        outb = out  + (size_t)b * (MAXIT + 1);

    float xv = xsol[b * NN + tid];
    float p = warp_sum(xv * xv);
    if (lane == 0) red[wid] = p;
    __syncthreads();
    float xtol = rtol[b] * sqrtf(red[0] + red[1] + red[2] + red[3] +
                                 red[4] + red[5] + red[6] + red[7]);
    __syncthreads();

    if (phase == 0) {
        float e0 = theta[b * NN + tid] - xv;
        e_sm[tid] = e0;
        float q = warp_sum(e0 * e0);
        if (lane == 0) red[wid] = q;
        __syncthreads();
        float err = sqrtf(red[0] + red[1] + red[2] + red[3] +
                          red[4] + red[5] + red[6] + red[7]);
        if (tid == 0) outb[0] = err;
        __syncthreads();
        int t = 0;
        while (err > xtol && t < MAXIT) {         // err uniform across CTA
            t++;
            err = iter_step(Gh, e_sm, red, wid, lane);
            if (tid == 0) outb[t] = err;
        }
        g_E[b * NN + tid] = e_sm[tid];
        if (tid == 0) { g_tc[b] = t; atomicMax(&g_T, t); }
    } else {
        int T = g_T, t = g_tc[b];
        e_sm[tid] = g_E[b * NN + tid];
        __syncthreads();
        while (t < T) {
            t++;
            float err = iter_step(Gh, e_sm, red, wid, lane);
            if (tid == 0) outb[t] = err;
        }
        for (int t2 = T + 1 + tid; t2 <= MAXIT; t2 += 256) outb[t2] = 0.0f;
    }
}

extern "C" void kernel_launch(void* const* d_in, const int* in_sizes, int n_in,
                              void* d_out, int out_size) {
    const float* A     = (const float*)d_in[0];
    const float* xsol  = (const float*)d_in[2];
    const float* theta = (const float*)d_in[3];
    const float* rtol  = (const float*)d_in[4];
    float*       out   = (float*)d_out;

    k_pre <<<BS, 128>>>(A);
    k_iter<<<BS, 256>>>(xsol, theta, rtol, out, 0);
    k_iter<<<BS, 256>>>(xsol, theta, rtol, out, 1);
}